// round 6
// baseline (speedup 1.0000x reference)
#include <cuda_runtime.h>
#include <cuda_fp16.h>
#include <cuda_fp8.h>
#include <math.h>

#define U_CNT 50000
#define I_CNT 25000
#define DIM 64
#define N_CNT 75000
#define E2 2000000
#define BSZ 4096
#define ND (N_CNT*DIM)
#define EPSV 0.2f
#define REG_LAMBDA 1e-4f
#define SSL_LAMBDA 0.2f
#define SCAN_BLOCKS 74   // ceil(75001/1024)
#define SSL_NSPLIT 32
#define BLDK 72
#define FSCALE 64.0f
#define INV_FSCALE 0.015625f

// ---- device scratch (static allocation only) ----
__device__ __align__(256) unsigned g_x8[N_CNT * 16];   // fp8x4 ping (x * 64)
__device__ __align__(256) unsigned g_y8[N_CNT * 16];   // fp8x4 pong
__device__ __align__(256) float g_sum[ND];
__device__ __align__(256) float g_cl[ND];
__device__ __align__(16) int2  g_epack[E2];
__device__ int g_off[N_CNT + 8];
__device__ int g_scan[N_CNT + 8];
__device__ int g_wp[N_CNT + 8];
__device__ int g_bsum[SCAN_BLOCKS];
__device__ int g_boff[SCAN_BLOCKS];
__device__ int g_ctr1, g_ctr2;
__device__ __align__(16) float g_vucl[BSZ*DIM];
__device__ __align__(16) float g_vuemb[BSZ*DIM];
__device__ __align__(16) float g_vicl[BSZ*DIM];
__device__ __align__(16) float g_viemb[BSZ*DIM];
__device__ __align__(16) __half2 g_h1[2 * BSZ * 32];
__device__ __align__(16) __half2 g_h2[2 * BSZ * 32];
__device__ float g_part[2 * BSZ * SSL_NSPLIT];
__device__ float g_acc[4];

__device__ __forceinline__ float wred(float v) {
#pragma unroll
    for (int o = 16; o; o >>= 1) v += __shfl_xor_sync(0xffffffffu, v, o);
    return v;
}
__device__ __forceinline__ float hred16(float v) {   // reduce within 16-lane halves
#pragma unroll
    for (int o = 8; o; o >>= 1) v += __shfl_xor_sync(0xffffffffu, v, o);
    return v;
}
__device__ __forceinline__ int wscan_i(int v, int lane) {
#pragma unroll
    for (int o = 1; o < 32; o <<= 1) {
        int t = __shfl_up_sync(0xffffffffu, v, o);
        if (lane >= o) v += t;
    }
    return v;
}
__device__ __forceinline__ float4 fp8x4_to_f4(unsigned u) {
    __half2_raw lo = __nv_cvt_fp8x2_to_halfraw2((__nv_fp8x2_storage_t)(u & 0xFFFFu), __NV_E4M3);
    __half2_raw hi = __nv_cvt_fp8x2_to_halfraw2((__nv_fp8x2_storage_t)(u >> 16), __NV_E4M3);
    float2 a = __half22float2(*(__half2*)&lo);
    float2 b = __half22float2(*(__half2*)&hi);
    return make_float4(a.x, a.y, b.x, b.y);
}
__device__ __forceinline__ unsigned f4_to_fp8x4(float4 v) {
    unsigned lo = (unsigned)__nv_cvt_float2_to_fp8x2(make_float2(v.x, v.y), __NV_SATFINITE, __NV_E4M3);
    unsigned hi = (unsigned)__nv_cvt_float2_to_fp8x2(make_float2(v.z, v.w), __NV_SATFINITE, __NV_E4M3);
    return lo | (hi << 16);
}

// ---- init: x8 = fp8(64 * concat(tables)); zero histogram + acc + counters ----
__global__ void k_init(const float* __restrict__ ut, const float* __restrict__ itab) {
    int i = blockIdx.x * blockDim.x + threadIdx.x;   // fp8x4 index
    if (i < N_CNT * 16) {
        int fi = i * 4;
        float4 v;
        if (fi < U_CNT * DIM) v = *(const float4*)(ut + fi);
        else                  v = *(const float4*)(itab + fi - U_CNT * DIM);
        g_x8[i] = f4_to_fp8x4(make_float4(v.x * FSCALE, v.y * FSCALE, v.z * FSCALE, v.w * FSCALE));
    }
    if (i <= N_CNT) g_off[i] = 0;
    if (i < 4) g_acc[i] = 0.f;
    if (i == 0) { g_ctr1 = 0; g_ctr2 = 0; }
}

__global__ void k_hist(const int* __restrict__ src) {
    int e = blockIdx.x * blockDim.x + threadIdx.x;
    if (e < E2) atomicAdd(&g_off[src[e] + 1], 1);
}

// ---- block scan; writes g_scan and g_wp; last block scans block totals into g_boff ----
__global__ void k_scan12() {
    __shared__ int ws[32];
    __shared__ int lastf;
    int i = blockIdx.x * 1024 + threadIdx.x;
    int v = (i <= N_CNT) ? g_off[i] : 0;
    int lane = threadIdx.x & 31, wid = threadIdx.x >> 5;
    int s = wscan_i(v, lane);
    if (lane == 31) ws[wid] = s;
    __syncthreads();
    if (wid == 0) { int t = ws[lane]; t = wscan_i(t, lane); ws[lane] = t; }
    __syncthreads();
    if (wid) s += ws[wid - 1];
    if (i <= N_CNT) {
        g_scan[i] = s;
        if (i < N_CNT) g_wp[i] = s;
    }
    if (threadIdx.x == 1023) g_bsum[blockIdx.x] = s;
    __threadfence();
    __syncthreads();
    if (threadIdx.x == 0) lastf = (atomicAdd(&g_ctr1, 1) == SCAN_BLOCKS - 1);
    __syncthreads();
    if (lastf && threadIdx.x < 32) {
        int v0 = (lane < SCAN_BLOCKS) ? g_bsum[lane] : 0;
        int v1 = (32 + lane < SCAN_BLOCKS) ? g_bsum[32 + lane] : 0;
        int v2 = (64 + lane < SCAN_BLOCKS) ? g_bsum[64 + lane] : 0;
        int s0 = wscan_i(v0, lane);
        int t0 = __shfl_sync(0xffffffffu, s0, 31);
        int s1 = wscan_i(v1, lane) + t0;
        int t1 = __shfl_sync(0xffffffffu, s1, 31);
        int s2 = wscan_i(v2, lane) + t1;
        if (lane < SCAN_BLOCKS) g_boff[lane] = s0 - v0;
        if (32 + lane < SCAN_BLOCKS) g_boff[32 + lane] = s1 - v1;
        if (64 + lane < SCAN_BLOCKS) g_boff[64 + lane] = s2 - v2;
    }
}

// ---- scatter: block offset added after the atomic (g_wp holds per-block-local scan) ----
__global__ void k_scatter(const int* __restrict__ src, const int* __restrict__ dst,
                          const float* __restrict__ val) {
    int e = blockIdx.x * blockDim.x + threadIdx.x;
    if (e >= E2) return;
    int r = src[e];
    int p = atomicAdd(&g_wp[r], 1) + g_boff[r >> 10];
    g_epack[p] = make_int2(dst[e], __float_as_int(val[e]));
}

// ---- fused layer: 2 edges per gather LDG (half-warps), epack via shuffle.
//      lanes 0-15 -> even edge, lanes 16-31 -> odd edge; each lane owns 4 dims. ----
__global__ void k_layer(const unsigned* __restrict__ xin, unsigned* __restrict__ xout,
                        const float* __restrict__ noise, float* __restrict__ cl, int first) {
    int gt = blockIdx.x * blockDim.x + threadIdx.x;
    int row = gt >> 5, lane = gt & 31;
    if (row >= N_CNT) return;
    int half = lane >> 4, li = lane & 15;
    int k = g_scan[row] + g_boff[row >> 10];
    int end = g_scan[row + 1] + g_boff[(row + 1) >> 10];
    float a0 = 0.f, a1 = 0.f, a2 = 0.f, a3 = 0.f;
    while (k < end) {
        int m = end - k; if (m > 32) m = 32;
        int2 ep = make_int2(0, 0);
        if (lane < m) ep = __ldg(&g_epack[k + lane]);
        int npair = (m + 1) >> 1;
#pragma unroll 4
        for (int p = 0; p < npair; p++) {
            int idx = 2 * p + half;
            int dst = __shfl_sync(0xffffffffu, ep.x, idx);
            float w = __int_as_float(__shfl_sync(0xffffffffu, ep.y, idx));
            // idx >= m -> source lane held (0,0): w = 0, dst = 0 (safe address)
            unsigned u = __ldg(xin + (size_t)dst * 16 + li);
            float4 f = fp8x4_to_f4(u);
            a0 = fmaf(w, f.x, a0);
            a1 = fmaf(w, f.y, a1);
            a2 = fmaf(w, f.z, a2);
            a3 = fmaf(w, f.w, a3);
        }
        k += m;
    }
    // combine even/odd halves (both halves end up with the full sum)
    a0 += __shfl_xor_sync(0xffffffffu, a0, 16);
    a1 += __shfl_xor_sync(0xffffffffu, a1, 16);
    a2 += __shfl_xor_sync(0xffffffffu, a2, 16);
    a3 += __shfl_xor_sync(0xffffffffu, a3, 16);
    a0 *= INV_FSCALE; a1 *= INV_FSCALE; a2 *= INV_FSCALE; a3 *= INV_FSCALE;
    size_t off = (size_t)row * DIM + li * 4;
    float4 nz = *(const float4*)(noise + off);   // both halves load same addr (broadcast)
    float ss = hred16(nz.x * nz.x + nz.y * nz.y + nz.z * nz.z + nz.w * nz.w);
    float sc = EPSV / fmaxf(sqrtf(ss), 1e-12f);
    a0 += ((a0 > 0.f) ? 1.f : ((a0 < 0.f) ? -1.f : 0.f)) * nz.x * sc;
    a1 += ((a1 > 0.f) ? 1.f : ((a1 < 0.f) ? -1.f : 0.f)) * nz.y * sc;
    a2 += ((a2 > 0.f) ? 1.f : ((a2 < 0.f) ? -1.f : 0.f)) * nz.z * sc;
    a3 += ((a3 > 0.f) ? 1.f : ((a3 < 0.f) ? -1.f : 0.f)) * nz.w * sc;
    if (half == 0) {
        if (xout) xout[(size_t)row * 16 + li] =
            f4_to_fp8x4(make_float4(a0 * FSCALE, a1 * FSCALE, a2 * FSCALE, a3 * FSCALE));
        float4 sm;
        if (first) sm = make_float4(a0, a1, a2, a3);
        else {
            sm = *(float4*)(g_sum + off);
            sm.x += a0; sm.y += a1; sm.z += a2; sm.w += a3;
        }
        *(float4*)(g_sum + off) = sm;
        if (cl) *(float4*)(cl + off) = make_float4(a0, a1, a2, a3);
    }
}

// ---- normalize + write fp32 copy and fp16 copy ----
__device__ __forceinline__ void norm_copy(const float* __restrict__ srcrow,
                                          float* __restrict__ dstrow,
                                          __half2* __restrict__ hdst, int lane) {
    float2 v = *(const float2*)(srcrow + lane * 2);
    float ss = wred(v.x * v.x + v.y * v.y);
    float inv = 1.f / fmaxf(sqrtf(ss), 1e-12f);
    float2 o = make_float2(v.x * inv, v.y * inv);
    *(float2*)(dstrow + lane * 2) = o;
    hdst[lane] = __floats2half2_rn(o.x, o.y);
}

// ---- merged prep (blocks [0,512)) + bpr (blocks [512,1024)) ----
__global__ void k_prepbpr(const int* __restrict__ user, const int* __restrict__ pos,
                          const int* __restrict__ neg,
                          const float* __restrict__ ut, const float* __restrict__ itab) {
    if (blockIdx.x < 512) {
        int gt = blockIdx.x * blockDim.x + threadIdx.x;
        int k = gt >> 5, lane = gt & 31;
        size_t ru = (size_t)user[k] * DIM;
        size_t ri = (size_t)(U_CNT + pos[k]) * DIM;
        norm_copy(g_cl + ru,  g_vucl  + (size_t)k * DIM, g_h1 + (size_t)k * 32, lane);
        norm_copy(g_sum + ru, g_vuemb + (size_t)k * DIM, g_h2 + (size_t)k * 32, lane);
        norm_copy(g_cl + ri,  g_vicl  + (size_t)k * DIM, g_h1 + (size_t)(BSZ + k) * 32, lane);
        norm_copy(g_sum + ri, g_viemb + (size_t)k * DIM, g_h2 + (size_t)(BSZ + k) * 32, lane);
        return;
    }
    __shared__ float sh0[8], sh1[8];
    int gt = (blockIdx.x - 512) * blockDim.x + threadIdx.x;
    int k = gt >> 5, lane = gt & 31, w = threadIdx.x >> 5;
    float sp = 0.f, rg = 0.f;
    {
        int iu = user[k], ip = pos[k], ineg = neg[k];
        const float c = 1.f / 3.f;
        float2 ue = *(const float2*)(g_sum + (size_t)iu * DIM + lane * 2);
        float2 pe = *(const float2*)(g_sum + (size_t)(U_CNT + ip) * DIM + lane * 2);
        float2 ne = *(const float2*)(g_sum + (size_t)(U_CNT + ineg) * DIM + lane * 2);
        ue.x *= c; ue.y *= c; pe.x *= c; pe.y *= c; ne.x *= c; ne.y *= c;
        float ps = wred(ue.x * pe.x + ue.y * pe.y);
        float ns = wred(ue.x * ne.x + ue.y * ne.y);
        float2 a = *(const float2*)(ut + (size_t)iu * DIM + lane * 2);
        float2 b = *(const float2*)(itab + (size_t)ip * DIM + lane * 2);
        float2 d = *(const float2*)(itab + (size_t)ineg * DIM + lane * 2);
        float r = wred(a.x * a.x + a.y * a.y + b.x * b.x + b.y * b.y + d.x * d.x + d.y * d.y);
        if (lane == 0) {
            float z = ns - ps;
            sp = fmaxf(z, 0.f) + log1pf(expf(-fabsf(z)));
            rg = r;
        }
    }
    if (lane == 0) { sh0[w] = sp; sh1[w] = rg; }
    __syncthreads();
    if (threadIdx.x == 0) {
        float a = 0.f, b = 0.f;
#pragma unroll
        for (int i = 0; i < 8; i++) { a += sh0[i]; b += sh1[i]; }
        atomicAdd(&g_acc[0], a);
        atomicAdd(&g_acc[1], b);
    }
}

// ---- SSL via HMMA: 128x128 tile of S = v1 @ v2^T; exp+rowsum epilogue in regs ----
__global__ void __launch_bounds__(256) k_sslmma() {
    __shared__ __align__(16) __half bt[128 * BLDK];
    const __half* h1 = (const __half*)(g_h1 + (size_t)blockIdx.z * BSZ * 32);
    const __half* h2 = (const __half*)(g_h2 + (size_t)blockIdx.z * BSZ * 32);
    int tid = threadIdx.x, warp = tid >> 5, lane = tid & 31;
    int r = lane >> 2, c = lane & 3;
    int j0 = blockIdx.y * 128;
    {
        int row = tid >> 1, off = (tid & 1) * 32;
        const uint4* src = (const uint4*)(h2 + (size_t)(j0 + row) * 64 + off);
        uint4* dst = (uint4*)(bt + row * BLDK + off);
#pragma unroll
        for (int i = 0; i < 4; i++) dst[i] = src[i];
    }
    int i0 = blockIdx.x * 128 + warp * 16;
    unsigned a[16];
    {
        const __half* A0 = h1 + (size_t)(i0 + r) * 64;
        const __half* A8 = h1 + (size_t)(i0 + r + 8) * 64;
#pragma unroll
        for (int kc = 0; kc < 4; kc++) {
            int k0 = kc * 16 + 2 * c;
            a[kc * 4 + 0] = *(const unsigned*)(A0 + k0);
            a[kc * 4 + 1] = *(const unsigned*)(A8 + k0);
            a[kc * 4 + 2] = *(const unsigned*)(A0 + k0 + 8);
            a[kc * 4 + 3] = *(const unsigned*)(A8 + k0 + 8);
        }
    }
    __syncthreads();
    float s_lo = 0.f, s_hi = 0.f;
#pragma unroll
    for (int nt = 0; nt < 16; nt++) {
        const __half* Bp = bt + (nt * 8 + r) * BLDK;
        float c0 = 0.f, c1 = 0.f, c2 = 0.f, c3 = 0.f;
#pragma unroll
        for (int kc = 0; kc < 4; kc++) {
            unsigned b0 = *(const unsigned*)(Bp + kc * 16 + 2 * c);
            unsigned b1 = *(const unsigned*)(Bp + kc * 16 + 2 * c + 8);
            asm volatile(
                "mma.sync.aligned.m16n8k16.row.col.f32.f16.f16.f32 "
                "{%0,%1,%2,%3}, {%4,%5,%6,%7}, {%8,%9}, {%0,%1,%2,%3};"
                : "+f"(c0), "+f"(c1), "+f"(c2), "+f"(c3)
                : "r"(a[kc * 4 + 0]), "r"(a[kc * 4 + 1]),
                  "r"(a[kc * 4 + 2]), "r"(a[kc * 4 + 3]),
                  "r"(b0), "r"(b1));
        }
        s_lo += __expf(fmaf(c0, 5.f, -5.f)) + __expf(fmaf(c1, 5.f, -5.f));
        s_hi += __expf(fmaf(c2, 5.f, -5.f)) + __expf(fmaf(c3, 5.f, -5.f));
    }
    s_lo += __shfl_xor_sync(0xffffffffu, s_lo, 1);
    s_lo += __shfl_xor_sync(0xffffffffu, s_lo, 2);
    s_hi += __shfl_xor_sync(0xffffffffu, s_hi, 1);
    s_hi += __shfl_xor_sync(0xffffffffu, s_hi, 2);
    if (c == 0) {
        size_t base = (size_t)blockIdx.z * BSZ;
        g_part[(base + i0 + r) * SSL_NSPLIT + blockIdx.y] = s_lo;
        g_part[(base + i0 + r + 8) * SSL_NSPLIT + blockIdx.y] = s_hi;
    }
}

// ---- SSL combine + final output (last block writes out) ----
__global__ void k_sslfin(const float* __restrict__ v1u, const float* __restrict__ v2u,
                         const float* __restrict__ v1i, const float* __restrict__ v2i,
                         float* __restrict__ out) {
    __shared__ float sh[8];
    const float* v1 = blockIdx.y ? v1i : v1u;
    const float* v2 = blockIdx.y ? v2i : v2u;
    int i = blockIdx.x * blockDim.x + threadIdx.x;
    float s = 0.f;
    size_t base = ((size_t)blockIdx.y * BSZ + i) * SSL_NSPLIT;
#pragma unroll
    for (int cc = 0; cc < SSL_NSPLIT; cc++) s += g_part[base + cc];
    float ttl = 5.0f + logf(s);
    const float4* af = (const float4*)v1 + (size_t)i * 16;
    const float4* bf = (const float4*)v2 + (size_t)i * 16;
    float pd = 0.f;
#pragma unroll
    for (int q = 0; q < 16; q++) {
        float4 x = af[q], y = bf[q];
        pd += x.x * y.x + x.y * y.y + x.z * y.z + x.w * y.w;
    }
    float val = ttl - pd * 5.0f;
    val = wred(val);
    int lane = threadIdx.x & 31, w = threadIdx.x >> 5;
    if (lane == 0) sh[w] = val;
    __syncthreads();
    if (threadIdx.x == 0) {
        float a = 0.f;
#pragma unroll
        for (int q = 0; q < 8; q++) a += sh[q];
        atomicAdd(&g_acc[2 + blockIdx.y], a);
        __threadfence();
        if (atomicAdd(&g_ctr2, 1) == 31) {
            out[0] = g_acc[0] / (float)BSZ;
            out[1] = REG_LAMBDA * 0.5f * g_acc[1] / (float)BSZ;
            out[2] = SSL_LAMBDA * ((g_acc[2] + g_acc[3]) / (float)BSZ);
        }
    }
}

extern "C" void kernel_launch(void* const* d_in, const int* in_sizes, int n_in,
                              void* d_out, int out_size) {
    const float* ut   = (const float*)d_in[0];
    const float* itab = (const float*)d_in[1];
    const float* eval = (const float*)d_in[2];
    const float* noise= (const float*)d_in[3];
    const int*   esrc = (const int*)d_in[4];
    const int*   edst = (const int*)d_in[5];
    const int*   user = (const int*)d_in[6];
    const int*   pos  = (const int*)d_in[7];
    const int*   neg  = (const int*)d_in[8];
    float* out = (float*)d_out;

    unsigned *px8, *py8;
    float *pcl, *pucl, *puemb, *picl, *piemb;
    cudaGetSymbolAddress((void**)&px8, g_x8);
    cudaGetSymbolAddress((void**)&py8, g_y8);
    cudaGetSymbolAddress((void**)&pcl, g_cl);
    cudaGetSymbolAddress((void**)&pucl, g_vucl);
    cudaGetSymbolAddress((void**)&puemb, g_vuemb);
    cudaGetSymbolAddress((void**)&picl, g_vicl);
    cudaGetSymbolAddress((void**)&piemb, g_viemb);

    const int eb = (E2 + 255) / 256;
    const int lb = (N_CNT * 32 + 255) / 256;

    k_init<<<(N_CNT * 16 + 255) / 256, 256>>>(ut, itab);
    k_hist<<<eb, 256>>>(esrc);
    k_scan12<<<SCAN_BLOCKS, 1024>>>();
    k_scatter<<<eb, 256>>>(esrc, edst, eval);

    k_layer<<<lb, 256>>>(px8, py8, noise, pcl, 1);
    k_layer<<<lb, 256>>>(py8, px8, noise + (size_t)ND, nullptr, 0);
    k_layer<<<lb, 256>>>(px8, nullptr, noise + 2 * (size_t)ND, nullptr, 0);

    k_prepbpr<<<1024, 256>>>(user, pos, neg, ut, itab);

    dim3 sg(BSZ / 128, BSZ / 128, 2);
    k_sslmma<<<sg, 256>>>();
    dim3 fg(BSZ / 256, 2);
    k_sslfin<<<fg, 256>>>(pucl, puemb, picl, piemb, out);
}